// round 14
// baseline (speedup 1.0000x reference)
#include <cuda_runtime.h>
#include <cuda_fp16.h>
#include <cstdint>

// ---------------- problem constants ----------------
#define Bsz   2
#define Tseq  1024
#define NQH   32
#define NKV   8
#define Dh    128
#define BM    64
#define BN    64
#define NQT   (Tseq / BM)     // 16
#define NTHREADS 128
#define LOG2E 1.4426950408889634f
#define MINIT (-1.0e30f)      // |MINIT*LOG2E| < FLT_MAX (NaN-safe)

// ---------------- pre-converted K/V blob (global scratch) ----------------
// per (b, kh, kt): KHI(16K) | KLO(16K) | VHI(16K), swizzled tile layout
#define KLO_OFF  16384
#define VHI_OFF  32768
#define BLOBSZ   49152
__device__ __align__(16) static char GKV[(size_t)Bsz * NKV * NQT * BLOBSZ];

// ---------------- smem layout ----------------
#define OFF_BUF0 0
#define OFF_BUF1 49152
#define OFF_SEG  98304            // 2 x 256B seg rows
#define SMEM_TOTAL (OFF_SEG + 512)   // 98,816 B -> 2 CTAs/SM

__device__ __forceinline__ uint32_t smem_u32(const void* p) {
    uint32_t a;
    asm("{ .reg .u64 t; cvta.to.shared.u64 t, %1; cvt.u32.u64 %0, t; }"
        : "=r"(a) : "l"(p));
    return a;
}
__device__ __forceinline__ uint32_t toff(int row, int c) {
    return ((uint32_t)row << 8) + (((uint32_t)(c ^ (row & 7))) << 4);
}
__device__ __forceinline__ void ldsm4(uint32_t* r, uint32_t a) {
    asm volatile("ldmatrix.sync.aligned.m8n8.x4.shared.b16 {%0,%1,%2,%3}, [%4];"
                 : "=r"(r[0]), "=r"(r[1]), "=r"(r[2]), "=r"(r[3]) : "r"(a));
}
__device__ __forceinline__ void ldsm4t(uint32_t* r, uint32_t a) {
    asm volatile("ldmatrix.sync.aligned.m8n8.x4.trans.shared.b16 {%0,%1,%2,%3}, [%4];"
                 : "=r"(r[0]), "=r"(r[1]), "=r"(r[2]), "=r"(r[3]) : "r"(a));
}
__device__ __forceinline__ void mma16816(float* d, const uint32_t* a, const uint32_t* b) {
    asm volatile("mma.sync.aligned.m16n8k16.row.col.f32.f16.f16.f32 "
                 "{%0,%1,%2,%3}, {%4,%5,%6,%7}, {%8,%9}, {%0,%1,%2,%3};"
                 : "+f"(d[0]), "+f"(d[1]), "+f"(d[2]), "+f"(d[3])
                 : "r"(a[0]), "r"(a[1]), "r"(a[2]), "r"(a[3]),
                   "r"(b[0]), "r"(b[1]));
}
__device__ __forceinline__ uint32_t pack_h2(float lo, float hi) {
    uint32_t r;
    asm("cvt.rn.f16x2.f32 %0, %1, %2;" : "=r"(r) : "f"(hi), "f"(lo));
    return r;
}
__device__ __forceinline__ uint32_t ex2_h2(uint32_t x) {
    uint32_t r;
    asm("ex2.approx.f16x2 %0, %1;" : "=r"(r) : "r"(x));
    return r;
}
__device__ __forceinline__ void split2(float x, float y, uint32_t& h, uint32_t& l) {
    __half hx = __float2half_rn(x), hy = __float2half_rn(y);
    __half lx = __float2half_rn(x - __half2float(hx));
    __half ly = __float2half_rn(y - __half2float(hy));
    __half2 hh = __halves2half2(hx, hy);
    __half2 ll = __halves2half2(lx, ly);
    h = *(uint32_t*)&hh;
    l = *(uint32_t*)&ll;
}
__device__ __forceinline__ void cvt_sts8(uint32_t ahi, uint32_t alo, const float* v) {
    uint32_t h[4], l[4];
    #pragma unroll
    for (int i = 0; i < 4; i++)
        split2(v[2*i], v[2*i+1], h[i], l[i]);
    asm volatile("st.shared.v4.b32 [%0], {%1,%2,%3,%4};"
                 :: "r"(ahi), "r"(h[0]), "r"(h[1]), "r"(h[2]), "r"(h[3]) : "memory");
    asm volatile("st.shared.v4.b32 [%0], {%1,%2,%3,%4};"
                 :: "r"(alo), "r"(l[0]), "r"(l[1]), "r"(l[2]), "r"(l[3]) : "memory");
}

#define CP16(sa, gp) \
    asm volatile("cp.async.cg.shared.global [%0], [%1], 16;" \
                 :: "r"(sa), "l"(gp) : "memory")
#define CP_COMMIT() asm volatile("cp.async.commit_group;" ::: "memory")
#define CP_WAIT1()  asm volatile("cp.async.wait_group 1;"  ::: "memory")

// first index in [0, r] whose seg equals seg[r] (seg ascending within batch)
__device__ __forceinline__ int seg_start(const int* __restrict__ seg, int base, int r) {
    const int sv = seg[base + r];
    int lo = 0, hi = r;
    while (lo < hi) {
        int mid = (lo + hi) >> 1;
        if (seg[base + mid] == sv) hi = mid; else lo = mid + 1;
    }
    return lo;
}

// ============ kernel 1: convert K,V -> fp16 hi/lo swizzled blobs ============
// 512 CTAs x 256 threads (half-tile each) for better wave balance on 148 SMs
__global__ __launch_bounds__(256)
void convert_kv(const float* __restrict__ K, const float* __restrict__ V)
{
    const int kt   = blockIdx.x >> 1;
    const int half = blockIdx.x & 1;
    const int kh = blockIdx.y, b = blockIdx.z;
    const int tid = threadIdx.x;
    char* blob = GKV + ((size_t)((b * NKV + kh) * NQT + kt)) * BLOBSZ;

    #pragma unroll
    for (int it = 0; it < 2; it++) {
        int idx = tid + it * 256;
        int r = (half << 5) + (idx >> 4);   // tile-local row 0..63
        int c = idx & 15;
        uint32_t o = toff(r, c);
        {
            const float* g = K + ((size_t)((b * Tseq + kt * BN + r) * NKV + kh)) * Dh + c * 8;
            float4 v0 = *(const float4*)g;
            float4 v1 = *(const float4*)(g + 4);
            float arr[8] = { v0.x, v0.y, v0.z, v0.w, v1.x, v1.y, v1.z, v1.w };
            uint32_t h[4], l[4];
            #pragma unroll
            for (int i = 0; i < 4; i++)
                split2(arr[2*i], arr[2*i+1], h[i], l[i]);
            *(uint4*)(blob + o)           = make_uint4(h[0], h[1], h[2], h[3]);
            *(uint4*)(blob + KLO_OFF + o) = make_uint4(l[0], l[1], l[2], l[3]);
        }
        {
            const float* g = V + ((size_t)((b * Tseq + kt * BN + r) * NKV + kh)) * Dh + c * 8;
            float4 v0 = *(const float4*)g;
            float4 v1 = *(const float4*)(g + 4);
            uint32_t h[4];
            h[0] = pack_h2(v0.x, v0.y); h[1] = pack_h2(v0.z, v0.w);
            h[2] = pack_h2(v1.x, v1.y); h[3] = pack_h2(v1.z, v1.w);
            *(uint4*)(blob + VHI_OFF + o) = make_uint4(h[0], h[1], h[2], h[3]);
        }
    }
}

// ============ kernel 2: attention ============
__global__ __launch_bounds__(NTHREADS, 2)
void attn_hmma_kernel(const float* __restrict__ Q,
                      const int*   __restrict__ seg,
                      float*       __restrict__ Out)
{
    extern __shared__ char smem[];
    const uint32_t sb = smem_u32(smem);
    const int tid  = threadIdx.x;
    const int wid  = tid >> 5;
    const int lane = tid & 31;
    const int quad = lane >> 2;
    const int qr   = lane & 3;

    const int qtile = (NQT - 1) - blockIdx.z;     // heavy-first
    const int h     = blockIdx.x;
    const int b     = blockIdx.y;
    const int kh    = h >> 2;
    const int q0    = qtile * BM;
    const int segbase = b * Tseq;

    const int sqmin = seg[segbase + q0];
    const int sqmax = seg[segbase + q0 + BM - 1];
    const int ktmax = qtile;
    auto inactive = [&](int t) -> bool {
        int s0 = seg[segbase + t * BN];
        int s1 = seg[segbase + t * BN + BN - 1];
        return (s1 < sqmin) | (s0 > sqmax);
    };
    const int kt_lo = seg_start(seg, segbase, q0) / BN;

    const char* blobs = GKV + ((size_t)(b * NKV + kh) * NQT) * BLOBSZ;
    auto issue_tile = [&](int t, int bf) {
        const char* gsrc = blobs + (size_t)t * BLOBSZ;
        uint32_t sdst = sb + (bf ? OFF_BUF1 : OFF_BUF0);
        #pragma unroll
        for (int it = 0; it < 24; it++) {
            uint32_t off = (uint32_t)tid * 16 + (uint32_t)it * 2048;
            CP16(sdst + off, gsrc + off);
        }
        if (tid < 16)
            CP16(sb + OFF_SEG + bf * 256 + tid * 16,
                 (const char*)(seg + segbase + t * BN) + tid * 16);
    };

    // ---- EARLY: first tile in flight before Q prologue (hides its latency) ----
    issue_tile(kt_lo, 0);
    CP_COMMIT();

    // ---- prologue: Q -> fp16 hi/lo staged in BUF1 (BUF0 busy with tile 0) ----
    #pragma unroll
    for (int it = 0; it < 8; it++) {
        int idx = tid + it * NTHREADS;
        int r = idx >> 4, c = idx & 15;
        const float* g = Q + ((size_t)((b * Tseq + q0 + r) * NQH + h)) * Dh + c * 8;
        float4 v0 = *(const float4*)g;
        float4 v1 = *(const float4*)(g + 4);
        float arr[8] = { v0.x, v0.y, v0.z, v0.w, v1.x, v1.y, v1.z, v1.w };
        uint32_t o = toff(r, c);
        cvt_sts8(sb + OFF_BUF1 + o, sb + OFF_BUF1 + KLO_OFF + o, arr);
    }
    __syncthreads();

    // fragment addressing
    const int rA    = 16 * wid + (lane & 15);
    const uint32_t aoff_base = (uint32_t)rA << 8;
    const int aswz   = rA & 7;
    const int achunk = lane >> 4;
    const int brow_l = ((lane >> 4) << 3) + (lane & 7);
    const int bsel   = (lane >> 3) & 1;
    const int bswz   = lane & 7;
    const int vrow_l = lane & 15;
    const int vsel   = lane >> 4;

    // persistent Q hi/lo fragments (from BUF1 staging)
    uint32_t Qh[8][4], Ql[8][4];
    #pragma unroll
    for (int k = 0; k < 8; k++) {
        uint32_t ao = aoff_base + ((uint32_t)(((k << 1) + achunk) ^ aswz) << 4);
        ldsm4(Qh[k], sb + OFF_BUF1 + ao);
        ldsm4(Ql[k], sb + OFF_BUF1 + KLO_OFF + ao);
    }
    __syncthreads();   // staging reads done; BUF1 reusable

    // second pipeline slot
    int nxt = kt_lo + 1;
    while (nxt <= ktmax && inactive(nxt)) nxt++;
    if (nxt <= ktmax) issue_tile(nxt, 1);
    CP_COMMIT();

    // rows + segment ranges (sorted contiguous segments)
    const int rowl0 = 16 * wid + quad;
    const int row0  = q0 + rowl0;
    const int row1  = row0 + 8;
    const int st0 = seg_start(seg, segbase, row0);
    const int st1 = seg_start(seg, segbase, row1);
    const int wmaxrow = q0 + 16 * wid + 15;

    float m0 = MINIT, m1 = MINIT, l0 = 0.0f, l1 = 0.0f;
    float Oa[16][4];
    #pragma unroll
    for (int i = 0; i < 16; i++)
        #pragma unroll
        for (int j = 0; j < 4; j++) Oa[i][j] = 0.0f;

    const float NEG = -__int_as_float(0x7f800000);   // -inf
    const uint32_t ONES2[2] = { 0x3C003C00u, 0x3C003C00u };

    int cur = kt_lo;
    int buf = 0;
    while (cur <= ktmax) {
        const int k0 = cur * BN;
        CP_WAIT1();
        __syncthreads();                           // tile 'cur' resident
        const uint32_t cbase = sb + (buf ? OFF_BUF1 : OFF_BUF0);
        const int* segCur = (const int*)(smem + OFF_SEG + buf * 256);

        // ---- QK: S = qh*kh + qh*kl + ql*kh (skip blocks above diagonal) ----
        float S[8][4];
        #pragma unroll
        for (int n = 0; n < 8; n++)
            #pragma unroll
            for (int j = 0; j < 4; j++) S[n][j] = 0.0f;

        #pragma unroll
        for (int np = 0; np < 4; np++) {
            if (k0 + np * 16 > wmaxrow) continue;   // warp-uniform causal skip
            #pragma unroll
            for (int k = 0; k < 8; k++) {
                uint32_t bh[4], bl[4];
                uint32_t bo = ((uint32_t)(np * 16 + brow_l) << 8)
                            + ((uint32_t)(((k << 1) + bsel) ^ bswz) << 4);
                ldsm4(bh, cbase + bo);
                ldsm4(bl, cbase + KLO_OFF + bo);
                mma16816(S[2*np],   Qh[k], bh);
                mma16816(S[2*np+1], Qh[k], bh + 2);
                mma16816(S[2*np],   Qh[k], bl);
                mma16816(S[2*np+1], Qh[k], bl + 2);
                mma16816(S[2*np],   Ql[k], bh);
                mma16816(S[2*np+1], Ql[k], bh + 2);
            }
        }

        // ---- masking (range compares) + row max ----
        float mx0 = m0, mx1 = m1;
        #pragma unroll
        for (int n = 0; n < 8; n++) {
            int cg = k0 + n * 8 + qr * 2;
            bool a00 = (cg     >= st0) && (cg     <= row0);
            bool a01 = (cg + 1 >= st0) && (cg + 1 <= row0);
            bool a10 = (cg     >= st1) && (cg     <= row1);
            bool a11 = (cg + 1 >= st1) && (cg + 1 <= row1);
            S[n][0] = a00 ? S[n][0] : NEG;
            S[n][1] = a01 ? S[n][1] : NEG;
            S[n][2] = a10 ? S[n][2] : NEG;
            S[n][3] = a11 ? S[n][3] : NEG;
            mx0 = fmaxf(mx0, fmaxf(S[n][0], S[n][1]));
            mx1 = fmaxf(mx1, fmaxf(S[n][2], S[n][3]));
        }
        mx0 = fmaxf(mx0, __shfl_xor_sync(0xffffffffu, mx0, 1));
        mx0 = fmaxf(mx0, __shfl_xor_sync(0xffffffffu, mx0, 2));
        mx1 = fmaxf(mx1, __shfl_xor_sync(0xffffffffu, mx1, 1));
        mx1 = fmaxf(mx1, __shfl_xor_sync(0xffffffffu, mx1, 2));

        float sc0 = __expf(m0 - mx0);
        float sc1 = __expf(m1 - mx1);
        m0 = mx0; m1 = mx1;

        // ---- exp2 fp16x2 -> P fragments ----
        const float c0 = -mx0 * LOG2E;
        const float c1 = -mx1 * LOG2E;
        uint32_t PH[4][4];
        #pragma unroll
        for (int n = 0; n < 8; n++) {
            float t0 = fmaf(S[n][0], LOG2E, c0);
            float t1 = fmaf(S[n][1], LOG2E, c0);
            float t2 = fmaf(S[n][2], LOG2E, c1);
            float t3 = fmaf(S[n][3], LOG2E, c1);
            uint32_t p01 = ex2_h2(pack_h2(t0, t1));
            uint32_t p23 = ex2_h2(pack_h2(t2, t3));
            PH[n >> 1][(n & 1) << 1]       = p01;
            PH[n >> 1][((n & 1) << 1) | 1] = p23;
        }

        // ---- row sums (ones-MMA) ----
        float Lacc[4] = { 0.0f, 0.0f, 0.0f, 0.0f };
        #pragma unroll
        for (int kc = 0; kc < 4; kc++) {
            if (k0 + kc * 16 > wmaxrow) continue;   // P block provably zero
            mma16816(Lacc, PH[kc], ONES2);
        }
        l0 = l0 * sc0 + Lacc[0];
        l1 = l1 * sc1 + Lacc[2];

        // ---- rescale O ----
        #pragma unroll
        for (int nd = 0; nd < 16; nd++) {
            Oa[nd][0] *= sc0; Oa[nd][1] *= sc0;
            Oa[nd][2] *= sc1; Oa[nd][3] *= sc1;
        }

        // ---- PV (skip zero P blocks) ----
        #pragma unroll
        for (int kc = 0; kc < 4; kc++) {
            if (k0 + kc * 16 > wmaxrow) continue;
            #pragma unroll
            for (int ndp = 0; ndp < 8; ndp++) {
                uint32_t vh[4];
                uint32_t vo = ((uint32_t)(kc * 16 + vrow_l) << 8)
                            + ((uint32_t)((2 * ndp + vsel) ^ bswz) << 4);
                ldsm4t(vh, cbase + VHI_OFF + vo);
                mma16816(Oa[2*ndp],   PH[kc], vh);
                mma16816(Oa[2*ndp+1], PH[kc], vh + 2);
            }
        }

        __syncthreads();                           // buf reads done
        int n2 = nxt + 1;
        while (n2 <= ktmax && inactive(n2)) n2++;
        if (n2 <= ktmax) issue_tile(n2, buf);
        CP_COMMIT();                               // one group per slot, always

        cur = nxt; nxt = n2; buf ^= 1;
    }

    // ---- epilogue ----
    const float inv0 = 1.0f / l0;
    const float inv1 = 1.0f / l1;
    float* o0 = Out + ((size_t)((b * Tseq + row0) * NQH + h)) * Dh;
    float* o1 = Out + ((size_t)((b * Tseq + row1) * NQH + h)) * Dh;
    #pragma unroll
    for (int nd = 0; nd < 16; nd++) {
        int d = nd * 8 + qr * 2;
        float2 w0 = make_float2(Oa[nd][0] * inv0, Oa[nd][1] * inv0);
        float2 w1 = make_float2(Oa[nd][2] * inv1, Oa[nd][3] * inv1);
        *(float2*)(o0 + d) = w0;
        *(float2*)(o1 + d) = w1;
    }
}

extern "C" void kernel_launch(void* const* d_in, const int* in_sizes, int n_in,
                              void* d_out, int out_size)
{
    const float* Q   = (const float*)d_in[0];
    const float* K   = (const float*)d_in[1];
    const float* V   = (const float*)d_in[2];
    const int*   seg = (const int*)d_in[3];
    float*       O   = (float*)d_out;

    dim3 cg(NQT * 2, NKV, Bsz);
    convert_kv<<<cg, 256>>>(K, V);

    cudaFuncSetAttribute(attn_hmma_kernel,
                         cudaFuncAttributeMaxDynamicSharedMemorySize, SMEM_TOTAL);
    dim3 grid(NQH, Bsz, NQT);
    attn_hmma_kernel<<<grid, NTHREADS, SMEM_TOTAL>>>(Q, seg, O);
}

// round 15
// speedup vs baseline: 1.0541x; 1.0541x over previous
#include <cuda_runtime.h>
#include <cuda_fp16.h>
#include <cstdint>

// ---------------- problem constants ----------------
#define Bsz   2
#define Tseq  1024
#define NQH   32
#define NKV   8
#define Dh    128
#define BM    64
#define BN    64
#define NQT   (Tseq / BM)     // 16
#define NTHREADS 128
#define LOG2E 1.4426950408889634f
#define MINIT (-1.0e30f)      // |MINIT*LOG2E| < FLT_MAX (NaN-safe)

// ---------------- pre-converted K/V blob (global scratch) ----------------
// per (b, kh, kt): KHI(16K) | KLO(16K) | VHI(16K), swizzled tile layout
#define KLO_OFF  16384
#define VHI_OFF  32768
#define BLOBSZ   49152
__device__ __align__(16) static char GKV[(size_t)Bsz * NKV * NQT * BLOBSZ];

// ---------------- smem layout ----------------
#define OFF_BUF0 0
#define OFF_BUF1 49152
#define OFF_SEG  98304            // 2 x 256B seg rows
#define SMEM_TOTAL (OFF_SEG + 512)   // 98,816 B -> 2 CTAs/SM

__device__ __forceinline__ uint32_t smem_u32(const void* p) {
    uint32_t a;
    asm("{ .reg .u64 t; cvta.to.shared.u64 t, %1; cvt.u32.u64 %0, t; }"
        : "=r"(a) : "l"(p));
    return a;
}
__device__ __forceinline__ uint32_t toff(int row, int c) {
    return ((uint32_t)row << 8) + (((uint32_t)(c ^ (row & 7))) << 4);
}
__device__ __forceinline__ void ldsm4(uint32_t* r, uint32_t a) {
    asm volatile("ldmatrix.sync.aligned.m8n8.x4.shared.b16 {%0,%1,%2,%3}, [%4];"
                 : "=r"(r[0]), "=r"(r[1]), "=r"(r[2]), "=r"(r[3]) : "r"(a));
}
__device__ __forceinline__ void ldsm4t(uint32_t* r, uint32_t a) {
    asm volatile("ldmatrix.sync.aligned.m8n8.x4.trans.shared.b16 {%0,%1,%2,%3}, [%4];"
                 : "=r"(r[0]), "=r"(r[1]), "=r"(r[2]), "=r"(r[3]) : "r"(a));
}
__device__ __forceinline__ void mma16816(float* d, const uint32_t* a, const uint32_t* b) {
    asm volatile("mma.sync.aligned.m16n8k16.row.col.f32.f16.f16.f32 "
                 "{%0,%1,%2,%3}, {%4,%5,%6,%7}, {%8,%9}, {%0,%1,%2,%3};"
                 : "+f"(d[0]), "+f"(d[1]), "+f"(d[2]), "+f"(d[3])
                 : "r"(a[0]), "r"(a[1]), "r"(a[2]), "r"(a[3]),
                   "r"(b[0]), "r"(b[1]));
}
__device__ __forceinline__ uint32_t pack_h2(float lo, float hi) {
    uint32_t r;
    asm("cvt.rn.f16x2.f32 %0, %1, %2;" : "=r"(r) : "f"(hi), "f"(lo));
    return r;
}
__device__ __forceinline__ uint32_t ex2_h2(uint32_t x) {
    uint32_t r;
    asm("ex2.approx.f16x2 %0, %1;" : "=r"(r) : "r"(x));
    return r;
}
__device__ __forceinline__ void split2(float x, float y, uint32_t& h, uint32_t& l) {
    __half hx = __float2half_rn(x), hy = __float2half_rn(y);
    __half lx = __float2half_rn(x - __half2float(hx));
    __half ly = __float2half_rn(y - __half2float(hy));
    __half2 hh = __halves2half2(hx, hy);
    __half2 ll = __halves2half2(lx, ly);
    h = *(uint32_t*)&hh;
    l = *(uint32_t*)&ll;
}
__device__ __forceinline__ void cvt_sts8(uint32_t ahi, uint32_t alo, const float* v) {
    uint32_t h[4], l[4];
    #pragma unroll
    for (int i = 0; i < 4; i++)
        split2(v[2*i], v[2*i+1], h[i], l[i]);
    asm volatile("st.shared.v4.b32 [%0], {%1,%2,%3,%4};"
                 :: "r"(ahi), "r"(h[0]), "r"(h[1]), "r"(h[2]), "r"(h[3]) : "memory");
    asm volatile("st.shared.v4.b32 [%0], {%1,%2,%3,%4};"
                 :: "r"(alo), "r"(l[0]), "r"(l[1]), "r"(l[2]), "r"(l[3]) : "memory");
}

#define CP16(sa, gp) \
    asm volatile("cp.async.cg.shared.global [%0], [%1], 16;" \
                 :: "r"(sa), "l"(gp) : "memory")
#define CP_COMMIT() asm volatile("cp.async.commit_group;" ::: "memory")
#define CP_WAIT1()  asm volatile("cp.async.wait_group 1;"  ::: "memory")

// first index in [0, r] whose seg equals seg[r] (seg ascending within batch)
__device__ __forceinline__ int seg_start(const int* __restrict__ seg, int base, int r) {
    const int sv = seg[base + r];
    int lo = 0, hi = r;
    while (lo < hi) {
        int mid = (lo + hi) >> 1;
        if (seg[base + mid] == sv) hi = mid; else lo = mid + 1;
    }
    return lo;
}

// ============ kernel 1: convert K,V -> fp16 hi/lo swizzled blobs ============
// 512 CTAs x 256 threads (half-tile each): finer waves on 148 SMs (verified R14)
__global__ __launch_bounds__(256)
void convert_kv(const float* __restrict__ K, const float* __restrict__ V)
{
    const int kt   = blockIdx.x >> 1;
    const int half = blockIdx.x & 1;
    const int kh = blockIdx.y, b = blockIdx.z;
    const int tid = threadIdx.x;
    char* blob = GKV + ((size_t)((b * NKV + kh) * NQT + kt)) * BLOBSZ;

    #pragma unroll
    for (int it = 0; it < 2; it++) {
        int idx = tid + it * 256;
        int r = (half << 5) + (idx >> 4);   // tile-local row 0..63
        int c = idx & 15;
        uint32_t o = toff(r, c);
        {
            const float* g = K + ((size_t)((b * Tseq + kt * BN + r) * NKV + kh)) * Dh + c * 8;
            float4 v0 = *(const float4*)g;
            float4 v1 = *(const float4*)(g + 4);
            float arr[8] = { v0.x, v0.y, v0.z, v0.w, v1.x, v1.y, v1.z, v1.w };
            uint32_t h[4], l[4];
            #pragma unroll
            for (int i = 0; i < 4; i++)
                split2(arr[2*i], arr[2*i+1], h[i], l[i]);
            *(uint4*)(blob + o)           = make_uint4(h[0], h[1], h[2], h[3]);
            *(uint4*)(blob + KLO_OFF + o) = make_uint4(l[0], l[1], l[2], l[3]);
        }
        {
            const float* g = V + ((size_t)((b * Tseq + kt * BN + r) * NKV + kh)) * Dh + c * 8;
            float4 v0 = *(const float4*)g;
            float4 v1 = *(const float4*)(g + 4);
            uint32_t h[4];
            h[0] = pack_h2(v0.x, v0.y); h[1] = pack_h2(v0.z, v0.w);
            h[2] = pack_h2(v1.x, v1.y); h[3] = pack_h2(v1.z, v1.w);
            *(uint4*)(blob + VHI_OFF + o) = make_uint4(h[0], h[1], h[2], h[3]);
        }
    }
}

// ============ kernel 2: attention (R9 champion, verbatim) ============
__global__ __launch_bounds__(NTHREADS, 2)
void attn_hmma_kernel(const float* __restrict__ Q,
                      const int*   __restrict__ seg,
                      float*       __restrict__ Out)
{
    extern __shared__ char smem[];
    const uint32_t sb = smem_u32(smem);
    const int tid  = threadIdx.x;
    const int wid  = tid >> 5;
    const int lane = tid & 31;
    const int quad = lane >> 2;
    const int qr   = lane & 3;

    const int qtile = (NQT - 1) - blockIdx.z;     // heavy-first
    const int h     = blockIdx.x;
    const int b     = blockIdx.y;
    const int kh    = h >> 2;
    const int q0    = qtile * BM;
    const int segbase = b * Tseq;

    // ---- prologue: Q -> fp16 hi/lo staged in BUF0 ----
    #pragma unroll
    for (int it = 0; it < 8; it++) {
        int idx = tid + it * NTHREADS;
        int r = idx >> 4, c = idx & 15;
        const float* g = Q + ((size_t)((b * Tseq + q0 + r) * NQH + h)) * Dh + c * 8;
        float4 v0 = *(const float4*)g;
        float4 v1 = *(const float4*)(g + 4);
        float arr[8] = { v0.x, v0.y, v0.z, v0.w, v1.x, v1.y, v1.z, v1.w };
        uint32_t o = toff(r, c);
        cvt_sts8(sb + OFF_BUF0 + o, sb + OFF_BUF0 + KLO_OFF + o, arr);
    }
    __syncthreads();

    // fragment addressing
    const int rA    = 16 * wid + (lane & 15);
    const uint32_t aoff_base = (uint32_t)rA << 8;
    const int aswz   = rA & 7;
    const int achunk = lane >> 4;
    const int brow_l = ((lane >> 4) << 3) + (lane & 7);
    const int bsel   = (lane >> 3) & 1;
    const int bswz   = lane & 7;
    const int vrow_l = lane & 15;
    const int vsel   = lane >> 4;

    // persistent Q hi/lo fragments
    uint32_t Qh[8][4], Ql[8][4];
    #pragma unroll
    for (int k = 0; k < 8; k++) {
        uint32_t ao = aoff_base + ((uint32_t)(((k << 1) + achunk) ^ aswz) << 4);
        ldsm4(Qh[k], sb + OFF_BUF0 + ao);
        ldsm4(Ql[k], sb + OFF_BUF0 + KLO_OFF + ao);
    }
    __syncthreads();   // staging reads done; BUF0 reusable

    // rows + segment ranges (sorted contiguous segments)
    const int rowl0 = 16 * wid + quad;
    const int row0  = q0 + rowl0;
    const int row1  = row0 + 8;
    const int st0 = seg_start(seg, segbase, row0);
    const int st1 = seg_start(seg, segbase, row1);
    const int wmaxrow = q0 + 16 * wid + 15;
    const int kt_lo = seg_start(seg, segbase, q0) / BN;

    const char* blobs = GKV + ((size_t)(b * NKV + kh) * NQT) * BLOBSZ;
    auto issue_tile = [&](int t, int bf) {
        const char* gsrc = blobs + (size_t)t * BLOBSZ;
        uint32_t sdst = sb + (bf ? OFF_BUF1 : OFF_BUF0);
        #pragma unroll
        for (int it = 0; it < 24; it++) {
            uint32_t off = (uint32_t)tid * 16 + (uint32_t)it * 2048;
            CP16(sdst + off, gsrc + off);
        }
    };

    issue_tile(kt_lo, 0);
    CP_COMMIT();
    if (kt_lo + 1 <= qtile) issue_tile(kt_lo + 1, 1);
    CP_COMMIT();

    float m0 = MINIT, m1 = MINIT, l0 = 0.0f, l1 = 0.0f;
    float Oa[16][4];
    #pragma unroll
    for (int i = 0; i < 16; i++)
        #pragma unroll
        for (int j = 0; j < 4; j++) Oa[i][j] = 0.0f;

    const float NEG = -__int_as_float(0x7f800000);   // -inf
    const uint32_t ONES2[2] = { 0x3C003C00u, 0x3C003C00u };

    int buf = 0;
    for (int kt = kt_lo; kt <= qtile; kt++, buf ^= 1) {
        const int k0 = kt * BN;
        CP_WAIT1();
        __syncthreads();
        const uint32_t cbase = sb + (buf ? OFF_BUF1 : OFF_BUF0);

        // ---- QK: S = qh*kh + qh*kl + ql*kh (skip blocks above diagonal) ----
        float S[8][4];
        #pragma unroll
        for (int n = 0; n < 8; n++)
            #pragma unroll
            for (int j = 0; j < 4; j++) S[n][j] = 0.0f;

        #pragma unroll
        for (int np = 0; np < 4; np++) {
            if (k0 + np * 16 > wmaxrow) continue;   // warp-uniform causal skip
            #pragma unroll
            for (int k = 0; k < 8; k++) {
                uint32_t bh[4], bl[4];
                uint32_t bo = ((uint32_t)(np * 16 + brow_l) << 8)
                            + ((uint32_t)(((k << 1) + bsel) ^ bswz) << 4);
                ldsm4(bh, cbase + bo);
                ldsm4(bl, cbase + KLO_OFF + bo);
                mma16816(S[2*np],   Qh[k], bh);
                mma16816(S[2*np+1], Qh[k], bh + 2);
                mma16816(S[2*np],   Qh[k], bl);
                mma16816(S[2*np+1], Qh[k], bl + 2);
                mma16816(S[2*np],   Ql[k], bh);
                mma16816(S[2*np+1], Ql[k], bh + 2);
            }
        }

        // ---- masking (range compares) + row max ----
        float mx0 = m0, mx1 = m1;
        #pragma unroll
        for (int n = 0; n < 8; n++) {
            int cg = k0 + n * 8 + qr * 2;
            bool a00 = (cg     >= st0) && (cg     <= row0);
            bool a01 = (cg + 1 >= st0) && (cg + 1 <= row0);
            bool a10 = (cg     >= st1) && (cg     <= row1);
            bool a11 = (cg + 1 >= st1) && (cg + 1 <= row1);
            S[n][0] = a00 ? S[n][0] : NEG;
            S[n][1] = a01 ? S[n][1] : NEG;
            S[n][2] = a10 ? S[n][2] : NEG;
            S[n][3] = a11 ? S[n][3] : NEG;
            mx0 = fmaxf(mx0, fmaxf(S[n][0], S[n][1]));
            mx1 = fmaxf(mx1, fmaxf(S[n][2], S[n][3]));
        }
        mx0 = fmaxf(mx0, __shfl_xor_sync(0xffffffffu, mx0, 1));
        mx0 = fmaxf(mx0, __shfl_xor_sync(0xffffffffu, mx0, 2));
        mx1 = fmaxf(mx1, __shfl_xor_sync(0xffffffffu, mx1, 1));
        mx1 = fmaxf(mx1, __shfl_xor_sync(0xffffffffu, mx1, 2));

        float sc0 = __expf(m0 - mx0);
        float sc1 = __expf(m1 - mx1);
        m0 = mx0; m1 = mx1;

        // ---- exp2 fp16x2 -> P fragments ----
        const float c0 = -mx0 * LOG2E;
        const float c1 = -mx1 * LOG2E;
        uint32_t PH[4][4];
        #pragma unroll
        for (int n = 0; n < 8; n++) {
            float t0 = fmaf(S[n][0], LOG2E, c0);
            float t1 = fmaf(S[n][1], LOG2E, c0);
            float t2 = fmaf(S[n][2], LOG2E, c1);
            float t3 = fmaf(S[n][3], LOG2E, c1);
            uint32_t p01 = ex2_h2(pack_h2(t0, t1));
            uint32_t p23 = ex2_h2(pack_h2(t2, t3));
            PH[n >> 1][(n & 1) << 1]       = p01;
            PH[n >> 1][((n & 1) << 1) | 1] = p23;
        }

        // ---- row sums (ones-MMA) ----
        float Lacc[4] = { 0.0f, 0.0f, 0.0f, 0.0f };
        #pragma unroll
        for (int kc = 0; kc < 4; kc++) {
            if (k0 + kc * 16 > wmaxrow) continue;   // P block provably zero
            mma16816(Lacc, PH[kc], ONES2);
        }
        l0 = l0 * sc0 + Lacc[0];
        l1 = l1 * sc1 + Lacc[2];

        // ---- rescale O ----
        #pragma unroll
        for (int nd = 0; nd < 16; nd++) {
            Oa[nd][0] *= sc0; Oa[nd][1] *= sc0;
            Oa[nd][2] *= sc1; Oa[nd][3] *= sc1;
        }

        // ---- PV (skip zero P blocks) ----
        #pragma unroll
        for (int kc = 0; kc < 4; kc++) {
            if (k0 + kc * 16 > wmaxrow) continue;
            #pragma unroll
            for (int ndp = 0; ndp < 8; ndp++) {
                uint32_t vh[4];
                uint32_t vo = ((uint32_t)(kc * 16 + vrow_l) << 8)
                            + ((uint32_t)((2 * ndp + vsel) ^ bswz) << 4);
                ldsm4t(vh, cbase + VHI_OFF + vo);
                mma16816(Oa[2*ndp],   PH[kc], vh);
                mma16816(Oa[2*ndp+1], PH[kc], vh + 2);
            }
        }

        __syncthreads();                           // buf reads done
        if (kt + 2 <= qtile) issue_tile(kt + 2, buf);
        CP_COMMIT();                               // one group per slot, always
    }

    // ---- epilogue ----
    const float inv0 = 1.0f / l0;
    const float inv1 = 1.0f / l1;
    float* o0 = Out + ((size_t)((b * Tseq + row0) * NQH + h)) * Dh;
    float* o1 = Out + ((size_t)((b * Tseq + row1) * NQH + h)) * Dh;
    #pragma unroll
    for (int nd = 0; nd < 16; nd++) {
        int d = nd * 8 + qr * 2;
        float2 w0 = make_float2(Oa[nd][0] * inv0, Oa[nd][1] * inv0);
        float2 w1 = make_float2(Oa[nd][2] * inv1, Oa[nd][3] * inv1);
        *(float2*)(o0 + d) = w0;
        *(float2*)(o1 + d) = w1;
    }
}

extern "C" void kernel_launch(void* const* d_in, const int* in_sizes, int n_in,
                              void* d_out, int out_size)
{
    const float* Q   = (const float*)d_in[0];
    const float* K   = (const float*)d_in[1];
    const float* V   = (const float*)d_in[2];
    const int*   seg = (const int*)d_in[3];
    float*       O   = (float*)d_out;

    dim3 cg(NQT * 2, NKV, Bsz);
    convert_kv<<<cg, 256>>>(K, V);

    cudaFuncSetAttribute(attn_hmma_kernel,
                         cudaFuncAttributeMaxDynamicSharedMemorySize, SMEM_TOTAL);
    dim3 grid(NQH, Bsz, NQT);
    attn_hmma_kernel<<<grid, NTHREADS, SMEM_TOTAL>>>(Q, seg, O);
}

// round 16
// speedup vs baseline: 1.0648x; 1.0102x over previous
#include <cuda_runtime.h>
#include <cuda_fp16.h>
#include <cstdint>

// ---------------- problem constants ----------------
#define Bsz   2
#define Tseq  1024
#define NQH   32
#define NKV   8
#define Dh    128
#define BM    64
#define BN    64
#define NQT   (Tseq / BM)     // 16
#define NTHREADS 128
#define LOG2E 1.4426950408889634f
#define MINIT (-1.0e30f)      // |MINIT*LOG2E| < FLT_MAX (NaN-safe)

// ---------------- pre-converted K/V blob (global scratch) ----------------
// per (b, kh, kt): KHI(16K) | KLO(16K) | VHI(16K), swizzled tile layout
#define KLO_OFF  16384
#define VHI_OFF  32768
#define BLOBSZ   49152
__device__ __align__(16) static char GKV[(size_t)Bsz * NKV * NQT * BLOBSZ];

// ---------------- smem layout ----------------
#define OFF_BUF0 0
#define OFF_BUF1 49152
#define OFF_SEG  98304            // 2 x 256B seg rows
#define SMEM_TOTAL (OFF_SEG + 512)   // 98,816 B -> 2 CTAs/SM

// ---------------- PDL (programmatic dependent launch) ----------------
#define GDC_LAUNCH_DEP() asm volatile("griddepcontrol.launch_dependents;")
#define GDC_WAIT()       asm volatile("griddepcontrol.wait;" ::: "memory")

__device__ __forceinline__ uint32_t smem_u32(const void* p) {
    uint32_t a;
    asm("{ .reg .u64 t; cvta.to.shared.u64 t, %1; cvt.u32.u64 %0, t; }"
        : "=r"(a) : "l"(p));
    return a;
}
__device__ __forceinline__ uint32_t toff(int row, int c) {
    return ((uint32_t)row << 8) + (((uint32_t)(c ^ (row & 7))) << 4);
}
__device__ __forceinline__ void ldsm4(uint32_t* r, uint32_t a) {
    asm volatile("ldmatrix.sync.aligned.m8n8.x4.shared.b16 {%0,%1,%2,%3}, [%4];"
                 : "=r"(r[0]), "=r"(r[1]), "=r"(r[2]), "=r"(r[3]) : "r"(a));
}
__device__ __forceinline__ void ldsm4t(uint32_t* r, uint32_t a) {
    asm volatile("ldmatrix.sync.aligned.m8n8.x4.trans.shared.b16 {%0,%1,%2,%3}, [%4];"
                 : "=r"(r[0]), "=r"(r[1]), "=r"(r[2]), "=r"(r[3]) : "r"(a));
}
__device__ __forceinline__ void mma16816(float* d, const uint32_t* a, const uint32_t* b) {
    asm volatile("mma.sync.aligned.m16n8k16.row.col.f32.f16.f16.f32 "
                 "{%0,%1,%2,%3}, {%4,%5,%6,%7}, {%8,%9}, {%0,%1,%2,%3};"
                 : "+f"(d[0]), "+f"(d[1]), "+f"(d[2]), "+f"(d[3])
                 : "r"(a[0]), "r"(a[1]), "r"(a[2]), "r"(a[3]),
                   "r"(b[0]), "r"(b[1]));
}
__device__ __forceinline__ uint32_t pack_h2(float lo, float hi) {
    uint32_t r;
    asm("cvt.rn.f16x2.f32 %0, %1, %2;" : "=r"(r) : "f"(hi), "f"(lo));
    return r;
}
__device__ __forceinline__ uint32_t ex2_h2(uint32_t x) {
    uint32_t r;
    asm("ex2.approx.f16x2 %0, %1;" : "=r"(r) : "r"(x));
    return r;
}
__device__ __forceinline__ void split2(float x, float y, uint32_t& h, uint32_t& l) {
    __half hx = __float2half_rn(x), hy = __float2half_rn(y);
    __half lx = __float2half_rn(x - __half2float(hx));
    __half ly = __float2half_rn(y - __half2float(hy));
    __half2 hh = __halves2half2(hx, hy);
    __half2 ll = __halves2half2(lx, ly);
    h = *(uint32_t*)&hh;
    l = *(uint32_t*)&ll;
}
__device__ __forceinline__ void cvt_sts8(uint32_t ahi, uint32_t alo, const float* v) {
    uint32_t h[4], l[4];
    #pragma unroll
    for (int i = 0; i < 4; i++)
        split2(v[2*i], v[2*i+1], h[i], l[i]);
    asm volatile("st.shared.v4.b32 [%0], {%1,%2,%3,%4};"
                 :: "r"(ahi), "r"(h[0]), "r"(h[1]), "r"(h[2]), "r"(h[3]) : "memory");
    asm volatile("st.shared.v4.b32 [%0], {%1,%2,%3,%4};"
                 :: "r"(alo), "r"(l[0]), "r"(l[1]), "r"(l[2]), "r"(l[3]) : "memory");
}

#define CP16(sa, gp) \
    asm volatile("cp.async.cg.shared.global [%0], [%1], 16;" \
                 :: "r"(sa), "l"(gp) : "memory")
#define CP_COMMIT() asm volatile("cp.async.commit_group;" ::: "memory")
#define CP_WAIT1()  asm volatile("cp.async.wait_group 1;"  ::: "memory")

// first index in [0, r] whose seg equals seg[r] (seg ascending within batch)
__device__ __forceinline__ int seg_start(const int* __restrict__ seg, int base, int r) {
    const int sv = seg[base + r];
    int lo = 0, hi = r;
    while (lo < hi) {
        int mid = (lo + hi) >> 1;
        if (seg[base + mid] == sv) hi = mid; else lo = mid + 1;
    }
    return lo;
}

// ============ kernel 1: convert K,V -> fp16 hi/lo swizzled blobs ============
// 512 CTAs x 256 threads (half-tile each); signals dependents immediately.
__global__ __launch_bounds__(256)
void convert_kv(const float* __restrict__ K, const float* __restrict__ V)
{
    GDC_LAUNCH_DEP();   // let attn grid launch & run its blob-independent prologue

    const int kt   = blockIdx.x >> 1;
    const int half = blockIdx.x & 1;
    const int kh = blockIdx.y, b = blockIdx.z;
    const int tid = threadIdx.x;
    char* blob = GKV + ((size_t)((b * NKV + kh) * NQT + kt)) * BLOBSZ;

    #pragma unroll
    for (int it = 0; it < 2; it++) {
        int idx = tid + it * 256;
        int r = (half << 5) + (idx >> 4);   // tile-local row 0..63
        int c = idx & 15;
        uint32_t o = toff(r, c);
        {
            const float* g = K + ((size_t)((b * Tseq + kt * BN + r) * NKV + kh)) * Dh + c * 8;
            float4 v0 = *(const float4*)g;
            float4 v1 = *(const float4*)(g + 4);
            float arr[8] = { v0.x, v0.y, v0.z, v0.w, v1.x, v1.y, v1.z, v1.w };
            uint32_t h[4], l[4];
            #pragma unroll
            for (int i = 0; i < 4; i++)
                split2(arr[2*i], arr[2*i+1], h[i], l[i]);
            *(uint4*)(blob + o)           = make_uint4(h[0], h[1], h[2], h[3]);
            *(uint4*)(blob + KLO_OFF + o) = make_uint4(l[0], l[1], l[2], l[3]);
        }
        {
            const float* g = V + ((size_t)((b * Tseq + kt * BN + r) * NKV + kh)) * Dh + c * 8;
            float4 v0 = *(const float4*)g;
            float4 v1 = *(const float4*)(g + 4);
            uint32_t h[4];
            h[0] = pack_h2(v0.x, v0.y); h[1] = pack_h2(v0.z, v0.w);
            h[2] = pack_h2(v1.x, v1.y); h[3] = pack_h2(v1.z, v1.w);
            *(uint4*)(blob + VHI_OFF + o) = make_uint4(h[0], h[1], h[2], h[3]);
        }
    }
}

// ============ kernel 2: attention (R9 champion + PDL wait) ============
__global__ __launch_bounds__(NTHREADS, 2)
void attn_hmma_kernel(const float* __restrict__ Q,
                      const int*   __restrict__ seg,
                      float*       __restrict__ Out)
{
    extern __shared__ char smem[];
    const uint32_t sb = smem_u32(smem);
    const int tid  = threadIdx.x;
    const int wid  = tid >> 5;
    const int lane = tid & 31;
    const int quad = lane >> 2;
    const int qr   = lane & 3;

    const int qtile = (NQT - 1) - blockIdx.z;     // heavy-first
    const int h     = blockIdx.x;
    const int b     = blockIdx.y;
    const int kh    = h >> 2;
    const int q0    = qtile * BM;
    const int segbase = b * Tseq;

    // ---- prologue (blob-independent; overlaps convert under PDL) ----
    #pragma unroll
    for (int it = 0; it < 8; it++) {
        int idx = tid + it * NTHREADS;
        int r = idx >> 4, c = idx & 15;
        const float* g = Q + ((size_t)((b * Tseq + q0 + r) * NQH + h)) * Dh + c * 8;
        float4 v0 = *(const float4*)g;
        float4 v1 = *(const float4*)(g + 4);
        float arr[8] = { v0.x, v0.y, v0.z, v0.w, v1.x, v1.y, v1.z, v1.w };
        uint32_t o = toff(r, c);
        cvt_sts8(sb + OFF_BUF0 + o, sb + OFF_BUF0 + KLO_OFF + o, arr);
    }
    __syncthreads();

    // fragment addressing
    const int rA    = 16 * wid + (lane & 15);
    const uint32_t aoff_base = (uint32_t)rA << 8;
    const int aswz   = rA & 7;
    const int achunk = lane >> 4;
    const int brow_l = ((lane >> 4) << 3) + (lane & 7);
    const int bsel   = (lane >> 3) & 1;
    const int bswz   = lane & 7;
    const int vrow_l = lane & 15;
    const int vsel   = lane >> 4;

    // persistent Q hi/lo fragments
    uint32_t Qh[8][4], Ql[8][4];
    #pragma unroll
    for (int k = 0; k < 8; k++) {
        uint32_t ao = aoff_base + ((uint32_t)(((k << 1) + achunk) ^ aswz) << 4);
        ldsm4(Qh[k], sb + OFF_BUF0 + ao);
        ldsm4(Ql[k], sb + OFF_BUF0 + KLO_OFF + ao);
    }
    __syncthreads();   // staging reads done; BUF0 reusable

    // rows + segment ranges (seg is harness input — no blob dependency)
    const int rowl0 = 16 * wid + quad;
    const int row0  = q0 + rowl0;
    const int row1  = row0 + 8;
    const int st0 = seg_start(seg, segbase, row0);
    const int st1 = seg_start(seg, segbase, row1);
    const int wmaxrow = q0 + 16 * wid + 15;
    const int kt_lo = seg_start(seg, segbase, q0) / BN;

    const char* blobs = GKV + ((size_t)(b * NKV + kh) * NQT) * BLOBSZ;
    auto issue_tile = [&](int t, int bf) {
        const char* gsrc = blobs + (size_t)t * BLOBSZ;
        uint32_t sdst = sb + (bf ? OFF_BUF1 : OFF_BUF0);
        #pragma unroll
        for (int it = 0; it < 24; it++) {
            uint32_t off = (uint32_t)tid * 16 + (uint32_t)it * 2048;
            CP16(sdst + off, gsrc + off);
        }
    };

    GDC_WAIT();   // blob must be complete from here on

    issue_tile(kt_lo, 0);
    CP_COMMIT();
    if (kt_lo + 1 <= qtile) issue_tile(kt_lo + 1, 1);
    CP_COMMIT();

    float m0 = MINIT, m1 = MINIT, l0 = 0.0f, l1 = 0.0f;
    float Oa[16][4];
    #pragma unroll
    for (int i = 0; i < 16; i++)
        #pragma unroll
        for (int j = 0; j < 4; j++) Oa[i][j] = 0.0f;

    const float NEG = -__int_as_float(0x7f800000);   // -inf
    const uint32_t ONES2[2] = { 0x3C003C00u, 0x3C003C00u };

    int buf = 0;
    for (int kt = kt_lo; kt <= qtile; kt++, buf ^= 1) {
        const int k0 = kt * BN;
        CP_WAIT1();
        __syncthreads();
        const uint32_t cbase = sb + (buf ? OFF_BUF1 : OFF_BUF0);

        // ---- QK: S = qh*kh + qh*kl + ql*kh (skip blocks above diagonal) ----
        float S[8][4];
        #pragma unroll
        for (int n = 0; n < 8; n++)
            #pragma unroll
            for (int j = 0; j < 4; j++) S[n][j] = 0.0f;

        #pragma unroll
        for (int np = 0; np < 4; np++) {
            if (k0 + np * 16 > wmaxrow) continue;   // warp-uniform causal skip
            #pragma unroll
            for (int k = 0; k < 8; k++) {
                uint32_t bh[4], bl[4];
                uint32_t bo = ((uint32_t)(np * 16 + brow_l) << 8)
                            + ((uint32_t)(((k << 1) + bsel) ^ bswz) << 4);
                ldsm4(bh, cbase + bo);
                ldsm4(bl, cbase + KLO_OFF + bo);
                mma16816(S[2*np],   Qh[k], bh);
                mma16816(S[2*np+1], Qh[k], bh + 2);
                mma16816(S[2*np],   Qh[k], bl);
                mma16816(S[2*np+1], Qh[k], bl + 2);
                mma16816(S[2*np],   Ql[k], bh);
                mma16816(S[2*np+1], Ql[k], bh + 2);
            }
        }

        // ---- masking (range compares) + row max ----
        float mx0 = m0, mx1 = m1;
        #pragma unroll
        for (int n = 0; n < 8; n++) {
            int cg = k0 + n * 8 + qr * 2;
            bool a00 = (cg     >= st0) && (cg     <= row0);
            bool a01 = (cg + 1 >= st0) && (cg + 1 <= row0);
            bool a10 = (cg     >= st1) && (cg     <= row1);
            bool a11 = (cg + 1 >= st1) && (cg + 1 <= row1);
            S[n][0] = a00 ? S[n][0] : NEG;
            S[n][1] = a01 ? S[n][1] : NEG;
            S[n][2] = a10 ? S[n][2] : NEG;
            S[n][3] = a11 ? S[n][3] : NEG;
            mx0 = fmaxf(mx0, fmaxf(S[n][0], S[n][1]));
            mx1 = fmaxf(mx1, fmaxf(S[n][2], S[n][3]));
        }
        mx0 = fmaxf(mx0, __shfl_xor_sync(0xffffffffu, mx0, 1));
        mx0 = fmaxf(mx0, __shfl_xor_sync(0xffffffffu, mx0, 2));
        mx1 = fmaxf(mx1, __shfl_xor_sync(0xffffffffu, mx1, 1));
        mx1 = fmaxf(mx1, __shfl_xor_sync(0xffffffffu, mx1, 2));

        float sc0 = __expf(m0 - mx0);
        float sc1 = __expf(m1 - mx1);
        m0 = mx0; m1 = mx1;

        // ---- exp2 fp16x2 -> P fragments ----
        const float c0 = -mx0 * LOG2E;
        const float c1 = -mx1 * LOG2E;
        uint32_t PH[4][4];
        #pragma unroll
        for (int n = 0; n < 8; n++) {
            float t0 = fmaf(S[n][0], LOG2E, c0);
            float t1 = fmaf(S[n][1], LOG2E, c0);
            float t2 = fmaf(S[n][2], LOG2E, c1);
            float t3 = fmaf(S[n][3], LOG2E, c1);
            uint32_t p01 = ex2_h2(pack_h2(t0, t1));
            uint32_t p23 = ex2_h2(pack_h2(t2, t3));
            PH[n >> 1][(n & 1) << 1]       = p01;
            PH[n >> 1][((n & 1) << 1) | 1] = p23;
        }

        // ---- row sums (ones-MMA) ----
        float Lacc[4] = { 0.0f, 0.0f, 0.0f, 0.0f };
        #pragma unroll
        for (int kc = 0; kc < 4; kc++) {
            if (k0 + kc * 16 > wmaxrow) continue;   // P block provably zero
            mma16816(Lacc, PH[kc], ONES2);
        }
        l0 = l0 * sc0 + Lacc[0];
        l1 = l1 * sc1 + Lacc[2];

        // ---- rescale O ----
        #pragma unroll
        for (int nd = 0; nd < 16; nd++) {
            Oa[nd][0] *= sc0; Oa[nd][1] *= sc0;
            Oa[nd][2] *= sc1; Oa[nd][3] *= sc1;
        }

        // ---- PV (skip zero P blocks) ----
        #pragma unroll
        for (int kc = 0; kc < 4; kc++) {
            if (k0 + kc * 16 > wmaxrow) continue;
            #pragma unroll
            for (int ndp = 0; ndp < 8; ndp++) {
                uint32_t vh[4];
                uint32_t vo = ((uint32_t)(kc * 16 + vrow_l) << 8)
                            + ((uint32_t)((2 * ndp + vsel) ^ bswz) << 4);
                ldsm4t(vh, cbase + VHI_OFF + vo);
                mma16816(Oa[2*ndp],   PH[kc], vh);
                mma16816(Oa[2*ndp+1], PH[kc], vh + 2);
            }
        }

        __syncthreads();                           // buf reads done
        if (kt + 2 <= qtile) issue_tile(kt + 2, buf);
        CP_COMMIT();                               // one group per slot, always
    }

    // ---- epilogue ----
    const float inv0 = 1.0f / l0;
    const float inv1 = 1.0f / l1;
    float* o0 = Out + ((size_t)((b * Tseq + row0) * NQH + h)) * Dh;
    float* o1 = Out + ((size_t)((b * Tseq + row1) * NQH + h)) * Dh;
    #pragma unroll
    for (int nd = 0; nd < 16; nd++) {
        int d = nd * 8 + qr * 2;
        float2 w0 = make_float2(Oa[nd][0] * inv0, Oa[nd][1] * inv0);
        float2 w1 = make_float2(Oa[nd][2] * inv1, Oa[nd][3] * inv1);
        *(float2*)(o0 + d) = w0;
        *(float2*)(o1 + d) = w1;
    }
}

extern "C" void kernel_launch(void* const* d_in, const int* in_sizes, int n_in,
                              void* d_out, int out_size)
{
    const float* Q   = (const float*)d_in[0];
    const float* K   = (const float*)d_in[1];
    const float* V   = (const float*)d_in[2];
    const int*   seg = (const int*)d_in[3];
    float*       O   = (float*)d_out;

    dim3 cg(NQT * 2, NKV, Bsz);
    convert_kv<<<cg, 256>>>(K, V);

    cudaFuncSetAttribute(attn_hmma_kernel,
                         cudaFuncAttributeMaxDynamicSharedMemorySize, SMEM_TOTAL);

    // PDL launch: attn may start while convert_kv is still running;
    // griddepcontrol.wait inside attn gates the blob reads.
    cudaLaunchConfig_t cfg = {};
    cfg.gridDim = dim3(NQH, Bsz, NQT);
    cfg.blockDim = dim3(NTHREADS, 1, 1);
    cfg.dynamicSmemBytes = SMEM_TOTAL;
    cfg.stream = 0;
    cudaLaunchAttribute attr[1];
    attr[0].id = cudaLaunchAttributeProgrammaticStreamSerialization;
    attr[0].val.programmaticStreamSerializationAllowed = 1;
    cfg.attrs = attr;
    cfg.numAttrs = 1;
    cudaLaunchKernelEx(&cfg, attn_hmma_kernel, Q, seg, O);
}